// round 1
// baseline (speedup 1.0000x reference)
#include <cuda_runtime.h>
#include <math_constants.h>
#include <stdint.h>

#define N_NODES 100000
#define N_EDGES 1600000
#define IN_DIM  128
#define OUT_DIM 64

// Scratch: device globals (no allocation allowed anywhere).
__device__ float g_z[(size_t)N_NODES * OUT_DIM];   // 25.6 MB
__device__ float g_e[N_EDGES];                     // 6.4 MB
__device__ float g_ee[N_EDGES];                    // 6.4 MB
__device__ float g_max[N_NODES];
__device__ float g_den[N_NODES];
__device__ int   g_idx64;

__device__ __forceinline__ long long ld_idx(const void* p, long long i, int w64) {
    if (w64) return ((const long long*)p)[i];
    return (long long)((const int*)p)[i];
}

__device__ __forceinline__ void atomicMaxFloat(float* addr, float v) {
    // Works with init = -inf. Positive floats compare correctly as ints,
    // negative floats compare inversely as uints.
    if (v >= 0.f) atomicMax((int*)addr, __float_as_int(v));
    else          atomicMin((unsigned int*)addr, __float_as_uint(v));
}

// ---------------------------------------------------------------------------
// K0: zero d_out, init segment max/denominator, detect index width (int32 vs int64)
// ---------------------------------------------------------------------------
__global__ void k_init(float* __restrict__ out, long long out_n, const void* srcp) {
    long long t = (long long)blockIdx.x * blockDim.x + threadIdx.x;
    long long i4 = t * 4;
    if (i4 + 3 < out_n) {
        *(float4*)(out + i4) = make_float4(0.f, 0.f, 0.f, 0.f);
    } else if (i4 < out_n) {
        for (long long j = i4; j < out_n; ++j) out[j] = 0.f;
    }
    if (t < N_NODES) {
        g_max[t] = -CUDART_INF_F;
        g_den[t] = 0.f;
    }
    if (t == 0) {
        // If data is int64 (values < 100000), every odd 32-bit word is 0.
        // If it is int32, odd words are random node ids; all-zero over 128
        // samples has probability ~(1e-5)^128.
        const int* p = (const int*)srcp;
        int w64 = 1;
        for (int i = 1; i < 256; i += 2)
            if (p[i] != 0) { w64 = 0; break; }
        g_idx64 = w64;
    }
}

// ---------------------------------------------------------------------------
// K1: z = h @ W^T  (fp32). 64-node x 64-out tile per block, 256 threads,
// 4x4 register micro-tile, k-major transposed shared (conflict-free).
// ---------------------------------------------------------------------------
__global__ void __launch_bounds__(256) k_gemm(const float* __restrict__ h,
                                              const float* __restrict__ W) {
    __shared__ float sm[2 * 64 * 64];      // hsT[64k][64n] + wsT[64k][64o], 32 KB
    float* hsT = sm;
    float* wsT = sm + 64 * 64;

    const int t  = threadIdx.x;
    const int nb = blockIdx.x * 64;
    const int tx = t & 15;      // node lane (stride-16 micro-tile)
    const int ty = t >> 4;      // out lane  (stride-16 micro-tile)

    float acc[4][4];
#pragma unroll
    for (int i = 0; i < 4; ++i)
#pragma unroll
        for (int j = 0; j < 4; ++j) acc[i][j] = 0.f;

#pragma unroll
    for (int c = 0; c < 2; ++c) {          // two K-chunks of 64
        const int kc = c * 64;
        __syncthreads();
#pragma unroll
        for (int r = 0; r < 4; ++r) {
            int idx  = t + r * 256;        // 0..1023
            int lane = idx & 63;           // node (or out row)
            int k4   = idx >> 6;           // 0..15 (float4 index within chunk)
            // h tile: lanes vary node -> STS conflict-free into k-major layout
            float4 v = make_float4(0.f, 0.f, 0.f, 0.f);
            int n = nb + lane;
            if (n < N_NODES)
                v = *(const float4*)(h + (size_t)n * IN_DIM + kc + k4 * 4);
            hsT[(k4 * 4 + 0) * 64 + lane] = v.x;
            hsT[(k4 * 4 + 1) * 64 + lane] = v.y;
            hsT[(k4 * 4 + 2) * 64 + lane] = v.z;
            hsT[(k4 * 4 + 3) * 64 + lane] = v.w;
            // W tile (64x128, L2-hot): same mapping
            float4 w = *(const float4*)(W + (size_t)lane * IN_DIM + kc + k4 * 4);
            wsT[(k4 * 4 + 0) * 64 + lane] = w.x;
            wsT[(k4 * 4 + 1) * 64 + lane] = w.y;
            wsT[(k4 * 4 + 2) * 64 + lane] = w.z;
            wsT[(k4 * 4 + 3) * 64 + lane] = w.w;
        }
        __syncthreads();
#pragma unroll 8
        for (int k = 0; k < 64; ++k) {
            float hv[4], wv[4];
#pragma unroll
            for (int i = 0; i < 4; ++i) hv[i] = hsT[k * 64 + tx + 16 * i];
#pragma unroll
            for (int j = 0; j < 4; ++j) wv[j] = wsT[k * 64 + ty + 16 * j];
#pragma unroll
            for (int i = 0; i < 4; ++i)
#pragma unroll
                for (int j = 0; j < 4; ++j)
                    acc[i][j] = fmaf(hv[i], wv[j], acc[i][j]);
        }
    }

    // Stage results through shared for coalesced global stores.
    __syncthreads();
    float* zs = sm;                         // 64 * 65 floats, fits in 32 KB
#pragma unroll
    for (int i = 0; i < 4; ++i)
#pragma unroll
        for (int j = 0; j < 4; ++j)
            zs[(tx + 16 * i) * 65 + (ty + 16 * j)] = acc[i][j];
    __syncthreads();
#pragma unroll
    for (int r = 0; r < 16; ++r) {
        int idx  = t + r * 256;             // 0..4095
        int node = idx >> 6;
        int o    = idx & 63;
        int n = nb + node;
        if (n < N_NODES)
            g_z[(size_t)n * OUT_DIM + o] = zs[node * 65 + o];
    }
}

// ---------------------------------------------------------------------------
// K2: per-edge score e = <z_src, z_dst>; atomic segment max over dst.
// 16 lanes per edge, float4 gathers (z is L2-resident), shfl reduce.
// ---------------------------------------------------------------------------
__global__ void __launch_bounds__(256) k_score(const void* __restrict__ srcp,
                                               const void* __restrict__ dstp) {
    long long g    = (long long)blockIdx.x * blockDim.x + threadIdx.x;
    long long edge = g >> 4;
    int lane       = (int)(g & 15);
    if (edge >= N_EDGES) return;
    int w64 = g_idx64;
    long long s = ld_idx(srcp, edge, w64);
    long long d = ld_idx(dstp, edge, w64);

    float4 a = ((const float4*)(g_z + s * OUT_DIM))[lane];
    float4 b = ((const float4*)(g_z + d * OUT_DIM))[lane];
    float p = a.x * b.x + a.y * b.y + a.z * b.z + a.w * b.w;
    p += __shfl_down_sync(0xffffffffu, p, 8, 16);
    p += __shfl_down_sync(0xffffffffu, p, 4, 16);
    p += __shfl_down_sync(0xffffffffu, p, 2, 16);
    p += __shfl_down_sync(0xffffffffu, p, 1, 16);
    if (lane == 0) {
        g_e[edge] = p;
        atomicMaxFloat(&g_max[d], p);
    }
}

// ---------------------------------------------------------------------------
// K3: e_exp = exp(e - max[dst]); atomic segment sum into denom.
// ---------------------------------------------------------------------------
__global__ void __launch_bounds__(256) k_expsum(const void* __restrict__ dstp) {
    long long i = (long long)blockIdx.x * blockDim.x + threadIdx.x;
    if (i >= N_EDGES) return;
    long long d = ld_idx(dstp, i, g_idx64);
    float ee = __expf(g_e[i] - g_max[d]);
    g_ee[i] = ee;
    atomicAdd(&g_den[d], ee);
}

// ---------------------------------------------------------------------------
// K4: out[dst] += (e_exp/denom[dst]) * z[src], via float4 vector atomics.
// ---------------------------------------------------------------------------
__global__ void __launch_bounds__(256) k_agg(const void* __restrict__ srcp,
                                             const void* __restrict__ dstp,
                                             float* __restrict__ out) {
    long long g    = (long long)blockIdx.x * blockDim.x + threadIdx.x;
    long long edge = g >> 4;
    int lane       = (int)(g & 15);
    if (edge >= N_EDGES) return;
    int w64 = g_idx64;
    long long s = ld_idx(srcp, edge, w64);
    long long d = ld_idx(dstp, edge, w64);

    float alpha = g_ee[edge] / fmaxf(g_den[d], 1e-30f);
    float4 zv = ((const float4*)(g_z + s * OUT_DIM))[lane];
    float4 v  = make_float4(zv.x * alpha, zv.y * alpha, zv.z * alpha, zv.w * alpha);
#if !defined(__CUDA_ARCH__) || (__CUDA_ARCH__ >= 900)
    atomicAdd(((float4*)(out + d * OUT_DIM)) + lane, v);
#else
    float* o = out + d * OUT_DIM + lane * 4;
    atomicAdd(o + 0, v.x);
    atomicAdd(o + 1, v.y);
    atomicAdd(o + 2, v.z);
    atomicAdd(o + 3, v.w);
#endif
}

// ---------------------------------------------------------------------------
extern "C" void kernel_launch(void* const* d_in, const int* in_sizes, int n_in,
                              void* d_out, int out_size) {
    const float* h   = (const float*)d_in[0];
    const float* W   = (const float*)d_in[1];
    const void*  src = d_in[2];
    const void*  dst = d_in[3];
    float* out = (float*)d_out;

    // K0: init (zero out, init max/den, detect index width)
    long long out_n = (long long)out_size;
    long long init_threads = out_n / 4 + 4;
    if (init_threads < N_NODES) init_threads = N_NODES;
    int init_blocks = (int)((init_threads + 255) / 256);
    k_init<<<init_blocks, 256>>>(out, out_n, src);

    // K1: GEMM z = h @ W^T
    k_gemm<<<(N_NODES + 63) / 64, 256>>>(h, W);

    // K2: edge scores + segment max (16 lanes/edge)
    long long score_threads = (long long)N_EDGES * 16;
    int sb = (int)((score_threads + 255) / 256);
    k_score<<<sb, 256>>>(src, dst);

    // K3: exp + segment sum
    k_expsum<<<(N_EDGES + 255) / 256, 256>>>(dst);

    // K4: weighted aggregation with vector atomics
    k_agg<<<sb, 256>>>(src, dst, out);
}

// round 3
// speedup vs baseline: 1.0380x; 1.0380x over previous
#include <cuda_runtime.h>
#include <math_constants.h>
#include <stdint.h>

#define N_NODES 100000
#define N_EDGES 1600000
#define IN_DIM  128
#define OUT_DIM 64

// Scratch: device globals (no allocation allowed anywhere).
__device__ float g_z[(size_t)N_NODES * OUT_DIM];   // 25.6 MB
__device__ float g_e[N_EDGES];                     // 6.4 MB
__device__ float g_max[N_NODES];
__device__ float g_den[N_NODES];
__device__ int   g_idx64;

__device__ __forceinline__ long long ld_idx(const void* p, long long i, int w64) {
    if (w64) return ((const long long*)p)[i];
    return (long long)((const int*)p)[i];
}

__device__ __forceinline__ void atomicMaxFloat(float* addr, float v) {
    // Works with init = -inf. Positive floats compare correctly as ints,
    // negative floats compare inversely as uints.
    if (v >= 0.f) atomicMax((int*)addr, __float_as_int(v));
    else          atomicMin((unsigned int*)addr, __float_as_uint(v));
}

// ---------------------------------------------------------------------------
// K0: zero d_out, init segment max/denominator, detect index width (int32 vs int64)
// ---------------------------------------------------------------------------
__global__ void k_init(float* __restrict__ out, long long out_n, const void* srcp) {
    long long t = (long long)blockIdx.x * blockDim.x + threadIdx.x;
    long long i4 = t * 4;
    if (i4 + 3 < out_n) {
        *(float4*)(out + i4) = make_float4(0.f, 0.f, 0.f, 0.f);
    } else if (i4 < out_n) {
        for (long long j = i4; j < out_n; ++j) out[j] = 0.f;
    }
    if (t < N_NODES) {
        g_max[t] = -CUDART_INF_F;
        g_den[t] = 0.f;
    }
    if (t == 0) {
        // If data is int64 (values < 100000), every odd 32-bit word is 0.
        // If it is int32, odd words are random node ids; all-zero over 128
        // samples has probability ~(1e-5)^128.
        const int* p = (const int*)srcp;
        int w64 = 1;
        for (int i = 1; i < 256; i += 2)
            if (p[i] != 0) { w64 = 0; break; }
        g_idx64 = w64;
    }
}

// ---------------------------------------------------------------------------
// K1: z = h @ W^T  (fp32). 64-node x 64-out tile per block, 256 threads,
// 4x4 register micro-tile, k-major transposed shared (conflict-free).
// ---------------------------------------------------------------------------
__global__ void __launch_bounds__(256) k_gemm(const float* __restrict__ h,
                                              const float* __restrict__ W) {
    __shared__ float sm[2 * 64 * 64];      // hsT[64k][64n] + wsT[64k][64o], 32 KB
    float* hsT = sm;
    float* wsT = sm + 64 * 64;

    const int t  = threadIdx.x;
    const int nb = blockIdx.x * 64;
    const int tx = t & 15;      // node lane (stride-16 micro-tile)
    const int ty = t >> 4;      // out lane  (stride-16 micro-tile)

    float acc[4][4];
#pragma unroll
    for (int i = 0; i < 4; ++i)
#pragma unroll
        for (int j = 0; j < 4; ++j) acc[i][j] = 0.f;

#pragma unroll
    for (int c = 0; c < 2; ++c) {          // two K-chunks of 64
        const int kc = c * 64;
        __syncthreads();
#pragma unroll
        for (int r = 0; r < 4; ++r) {
            int idx  = t + r * 256;        // 0..1023
            int lane = idx & 63;           // node (or out row)
            int k4   = idx >> 6;           // 0..15 (float4 index within chunk)
            // h tile: lanes vary node -> STS conflict-free into k-major layout
            float4 v = make_float4(0.f, 0.f, 0.f, 0.f);
            int n = nb + lane;
            if (n < N_NODES)
                v = *(const float4*)(h + (size_t)n * IN_DIM + kc + k4 * 4);
            hsT[(k4 * 4 + 0) * 64 + lane] = v.x;
            hsT[(k4 * 4 + 1) * 64 + lane] = v.y;
            hsT[(k4 * 4 + 2) * 64 + lane] = v.z;
            hsT[(k4 * 4 + 3) * 64 + lane] = v.w;
            // W tile (64x128, L2-hot): same mapping
            float4 w = *(const float4*)(W + (size_t)lane * IN_DIM + kc + k4 * 4);
            wsT[(k4 * 4 + 0) * 64 + lane] = w.x;
            wsT[(k4 * 4 + 1) * 64 + lane] = w.y;
            wsT[(k4 * 4 + 2) * 64 + lane] = w.z;
            wsT[(k4 * 4 + 3) * 64 + lane] = w.w;
        }
        __syncthreads();
#pragma unroll 8
        for (int k = 0; k < 64; ++k) {
            float hv[4], wv[4];
#pragma unroll
            for (int i = 0; i < 4; ++i) hv[i] = hsT[k * 64 + tx + 16 * i];
#pragma unroll
            for (int j = 0; j < 4; ++j) wv[j] = wsT[k * 64 + ty + 16 * j];
#pragma unroll
            for (int i = 0; i < 4; ++i)
#pragma unroll
                for (int j = 0; j < 4; ++j)
                    acc[i][j] = fmaf(hv[i], wv[j], acc[i][j]);
        }
    }

    // Stage results through shared for coalesced global stores.
    __syncthreads();
    float* zs = sm;                         // 64 * 65 floats, fits in 32 KB
#pragma unroll
    for (int i = 0; i < 4; ++i)
#pragma unroll
        for (int j = 0; j < 4; ++j)
            zs[(tx + 16 * i) * 65 + (ty + 16 * j)] = acc[i][j];
    __syncthreads();
#pragma unroll
    for (int r = 0; r < 16; ++r) {
        int idx  = t + r * 256;             // 0..4095
        int node = idx >> 6;
        int o    = idx & 63;
        int n = nb + node;
        if (n < N_NODES)
            g_z[(size_t)n * OUT_DIM + o] = zs[node * 65 + o];
    }
}

// ---------------------------------------------------------------------------
// K2: per-edge score e = <z_src, z_dst>; atomic segment max over dst.
// 16 lanes per edge, float4 gathers (z is L2-resident), shfl reduce.
// ---------------------------------------------------------------------------
__global__ void __launch_bounds__(256) k_score(const void* __restrict__ srcp,
                                               const void* __restrict__ dstp) {
    long long g    = (long long)blockIdx.x * blockDim.x + threadIdx.x;
    long long edge = g >> 4;
    int lane       = (int)(g & 15);
    if (edge >= N_EDGES) return;
    int w64 = g_idx64;
    long long s = ld_idx(srcp, edge, w64);
    long long d = ld_idx(dstp, edge, w64);

    float4 a = ((const float4*)(g_z + s * OUT_DIM))[lane];
    float4 b = ((const float4*)(g_z + d * OUT_DIM))[lane];
    float p = a.x * b.x + a.y * b.y + a.z * b.z + a.w * b.w;
    p += __shfl_down_sync(0xffffffffu, p, 8, 16);
    p += __shfl_down_sync(0xffffffffu, p, 4, 16);
    p += __shfl_down_sync(0xffffffffu, p, 2, 16);
    p += __shfl_down_sync(0xffffffffu, p, 1, 16);
    if (lane == 0) {
        g_e[edge] = p;
        atomicMaxFloat(&g_max[d], p);
    }
}

// ---------------------------------------------------------------------------
// K3: fused exp + denominator + UNNORMALIZED aggregation:
//   ee = exp(e - max[dst]);  den[dst] += ee;  out[dst] += ee * z[src]
// (normalization deferred to k_div -> removes the old k_expsum pass entirely)
// ---------------------------------------------------------------------------
__global__ void __launch_bounds__(256) k_agg(const void* __restrict__ srcp,
                                             const void* __restrict__ dstp,
                                             float* __restrict__ out) {
    long long g    = (long long)blockIdx.x * blockDim.x + threadIdx.x;
    long long edge = g >> 4;
    int lane       = (int)(g & 15);
    if (edge >= N_EDGES) return;
    int w64 = g_idx64;
    long long s = ld_idx(srcp, edge, w64);
    long long d = ld_idx(dstp, edge, w64);

    // e[edge] and max[d] loads are identical across the 16 lanes of this edge
    // -> coalesce to one request + broadcast.
    float ee = __expf(g_e[edge] - g_max[d]);
    if (lane == 0) atomicAdd(&g_den[d], ee);

    float4 zv = ((const float4*)(g_z + s * OUT_DIM))[lane];
    float4 v  = make_float4(zv.x * ee, zv.y * ee, zv.z * ee, zv.w * ee);
#if !defined(__CUDA_ARCH__) || (__CUDA_ARCH__ >= 900)
    atomicAdd(((float4*)(out + d * OUT_DIM)) + lane, v);
#else
    float* o = out + d * OUT_DIM + lane * 4;
    atomicAdd(o + 0, v.x);
    atomicAdd(o + 1, v.y);
    atomicAdd(o + 2, v.z);
    atomicAdd(o + 3, v.w);
#endif
}

// ---------------------------------------------------------------------------
// K4: normalize out[n][:] /= max(den[n], 1e-30). float4 vectorized.
// ---------------------------------------------------------------------------
__global__ void __launch_bounds__(256) k_div(float* __restrict__ out) {
    long long i = (long long)blockIdx.x * blockDim.x + threadIdx.x; // float4 idx
    long long total4 = (long long)N_NODES * OUT_DIM / 4;            // 1.6M
    if (i >= total4) return;
    long long node = i >> 4;                  // 16 float4 per node
    float inv = __frcp_rn(fmaxf(g_den[node], 1e-30f));
    float4 v = ((float4*)out)[i];
    v.x *= inv; v.y *= inv; v.z *= inv; v.w *= inv;
    ((float4*)out)[i] = v;
}

// ---------------------------------------------------------------------------
extern "C" void kernel_launch(void* const* d_in, const int* in_sizes, int n_in,
                              void* d_out, int out_size) {
    const float* h   = (const float*)d_in[0];
    const float* W   = (const float*)d_in[1];
    const void*  src = d_in[2];
    const void*  dst = d_in[3];
    float* out = (float*)d_out;

    // K0: init (zero out, init max/den, detect index width)
    long long out_n = (long long)out_size;
    long long init_threads = out_n / 4 + 4;
    if (init_threads < N_NODES) init_threads = N_NODES;
    int init_blocks = (int)((init_threads + 255) / 256);
    k_init<<<init_blocks, 256>>>(out, out_n, src);

    // K1: GEMM z = h @ W^T
    k_gemm<<<(N_NODES + 63) / 64, 256>>>(h, W);

    // K2: edge scores + segment max (16 lanes/edge)
    long long score_threads = (long long)N_EDGES * 16;
    int sb = (int)((score_threads + 255) / 256);
    k_score<<<sb, 256>>>(src, dst);

    // K3: fused exp + den + unnormalized aggregation
    k_agg<<<sb, 256>>>(src, dst, out);

    // K4: normalize
    long long div_threads = (long long)N_NODES * OUT_DIM / 4;
    k_div<<<(int)((div_threads + 255) / 256), 256>>>(out);
}

// round 6
// speedup vs baseline: 1.4335x; 1.3809x over previous
#include <cuda_runtime.h>
#include <math_constants.h>
#include <stdint.h>

#define N_NODES 100000
#define N_EDGES 1600000
#define IN_DIM  128
#define OUT_DIM 64

#define SCAN_CHUNK 1024
#define NBLK_SCAN  ((N_NODES + SCAN_CHUNK - 1) / SCAN_CHUNK)   // 98

// Scratch: device globals (no allocation allowed anywhere).
__device__ float g_z[(size_t)N_NODES * OUT_DIM];   // 25.6 MB
__device__ int   g_cnt[N_NODES];
__device__ int   g_off[N_NODES + 1];
__device__ int   g_cur[N_NODES];
__device__ int   g_bsum[NBLK_SCAN];
__device__ int   g_esrc[N_EDGES];                  // src node per dst-sorted edge
__device__ int   g_idx64;

__device__ __forceinline__ long long ld_idx(const void* p, long long i, int w64) {
    if (w64) return ((const long long*)p)[i];
    return (long long)((const int*)p)[i];
}

// ---------------------------------------------------------------------------
// K0: zero histogram counters; detect index width (int32 vs int64).
// ---------------------------------------------------------------------------
__global__ void k_init(const void* srcp) {
    int t = blockIdx.x * blockDim.x + threadIdx.x;
    if (t < N_NODES) g_cnt[t] = 0;
    if (t == 0) {
        // int64 indices < 100000 -> every odd 32-bit word is 0.
        const int* p = (const int*)srcp;
        int w64 = 1;
        for (int i = 1; i < 256; i += 2)
            if (p[i] != 0) { w64 = 0; break; }
        g_idx64 = w64;
    }
}

// ---------------------------------------------------------------------------
// K1: z = h @ W^T  (fp32). 64x64 tile, 256 threads, 4x4 micro-tile.
// ---------------------------------------------------------------------------
__global__ void __launch_bounds__(256) k_gemm(const float* __restrict__ h,
                                              const float* __restrict__ W) {
    __shared__ float sm[2 * 64 * 64];
    float* hsT = sm;
    float* wsT = sm + 64 * 64;

    const int t  = threadIdx.x;
    const int nb = blockIdx.x * 64;
    const int tx = t & 15;
    const int ty = t >> 4;

    float acc[4][4];
#pragma unroll
    for (int i = 0; i < 4; ++i)
#pragma unroll
        for (int j = 0; j < 4; ++j) acc[i][j] = 0.f;

#pragma unroll
    for (int c = 0; c < 2; ++c) {
        const int kc = c * 64;
        __syncthreads();
#pragma unroll
        for (int r = 0; r < 4; ++r) {
            int idx  = t + r * 256;
            int lane = idx & 63;
            int k4   = idx >> 6;
            float4 v = make_float4(0.f, 0.f, 0.f, 0.f);
            int n = nb + lane;
            if (n < N_NODES)
                v = *(const float4*)(h + (size_t)n * IN_DIM + kc + k4 * 4);
            hsT[(k4 * 4 + 0) * 64 + lane] = v.x;
            hsT[(k4 * 4 + 1) * 64 + lane] = v.y;
            hsT[(k4 * 4 + 2) * 64 + lane] = v.z;
            hsT[(k4 * 4 + 3) * 64 + lane] = v.w;
            float4 w = *(const float4*)(W + (size_t)lane * IN_DIM + kc + k4 * 4);
            wsT[(k4 * 4 + 0) * 64 + lane] = w.x;
            wsT[(k4 * 4 + 1) * 64 + lane] = w.y;
            wsT[(k4 * 4 + 2) * 64 + lane] = w.z;
            wsT[(k4 * 4 + 3) * 64 + lane] = w.w;
        }
        __syncthreads();
#pragma unroll 8
        for (int k = 0; k < 64; ++k) {
            float hv[4], wv[4];
#pragma unroll
            for (int i = 0; i < 4; ++i) hv[i] = hsT[k * 64 + tx + 16 * i];
#pragma unroll
            for (int j = 0; j < 4; ++j) wv[j] = wsT[k * 64 + ty + 16 * j];
#pragma unroll
            for (int i = 0; i < 4; ++i)
#pragma unroll
                for (int j = 0; j < 4; ++j)
                    acc[i][j] = fmaf(hv[i], wv[j], acc[i][j]);
        }
    }

    __syncthreads();
    float* zs = sm;
#pragma unroll
    for (int i = 0; i < 4; ++i)
#pragma unroll
        for (int j = 0; j < 4; ++j)
            zs[(tx + 16 * i) * 65 + (ty + 16 * j)] = acc[i][j];
    __syncthreads();
#pragma unroll
    for (int r = 0; r < 16; ++r) {
        int idx  = t + r * 256;
        int node = idx >> 6;
        int o    = idx & 63;
        int n = nb + node;
        if (n < N_NODES)
            g_z[(size_t)n * OUT_DIM + o] = zs[node * 65 + o];
    }
}

// ---------------------------------------------------------------------------
// K2: histogram of dst.
// ---------------------------------------------------------------------------
__global__ void __launch_bounds__(256) k_hist(const void* __restrict__ dstp) {
    long long i = (long long)blockIdx.x * blockDim.x + threadIdx.x;
    if (i >= N_EDGES) return;
    int d = (int)ld_idx(dstp, i, g_idx64);
    atomicAdd(&g_cnt[d], 1);
}

// ---------------------------------------------------------------------------
// K3a: per-chunk (1024 counts) exclusive scan; block totals to g_bsum.
// ---------------------------------------------------------------------------
__global__ void __launch_bounds__(256) k_scan1() {
    __shared__ int sh[256];
    int b = blockIdx.x, t = threadIdx.x;
    int base = b * SCAN_CHUNK + t * 4;
    int c[4], s = 0;
#pragma unroll
    for (int i = 0; i < 4; ++i) {
        int idx = base + i;
        c[i] = (idx < N_NODES) ? g_cnt[idx] : 0;
        s += c[i];
    }
    sh[t] = s;
    __syncthreads();
#pragma unroll
    for (int d = 1; d < 256; d <<= 1) {
        int v = (t >= d) ? sh[t - d] : 0;
        __syncthreads();
        sh[t] += v;
        __syncthreads();
    }
    int run = sh[t] - s;           // exclusive prefix for this thread
#pragma unroll
    for (int i = 0; i < 4; ++i) {
        int idx = base + i;
        if (idx < N_NODES) g_off[idx] = run;
        run += c[i];
    }
    if (t == 255) g_bsum[b] = sh[255];
}

// ---------------------------------------------------------------------------
// K3b: exclusive scan of the 98 block sums (single block).
// ---------------------------------------------------------------------------
__global__ void __launch_bounds__(128) k_scan2() {
    __shared__ int sh[128];
    int t = threadIdx.x;
    int v0 = (t < NBLK_SCAN) ? g_bsum[t] : 0;
    sh[t] = v0;
    __syncthreads();
#pragma unroll
    for (int d = 1; d < 128; d <<= 1) {
        int v = (t >= d) ? sh[t - d] : 0;
        __syncthreads();
        sh[t] += v;
        __syncthreads();
    }
    if (t < NBLK_SCAN) g_bsum[t] = sh[t] - v0;   // exclusive
}

// ---------------------------------------------------------------------------
// K3c: add block bases; init scatter cursors; seal g_off[N].
// ---------------------------------------------------------------------------
__global__ void __launch_bounds__(256) k_scan3() {
    int i = blockIdx.x * blockDim.x + threadIdx.x;
    if (i < N_NODES) {
        int o = g_off[i] + g_bsum[i >> 10];
        g_off[i] = o;
        g_cur[i] = o;
    }
    if (i == 0) g_off[N_NODES] = N_EDGES;
}

// ---------------------------------------------------------------------------
// K4: scatter src ids into dst-sorted order.
// ---------------------------------------------------------------------------
__global__ void __launch_bounds__(256) k_scatter(const void* __restrict__ srcp,
                                                 const void* __restrict__ dstp) {
    long long i = (long long)blockIdx.x * blockDim.x + threadIdx.x;
    if (i >= N_EDGES) return;
    int w64 = g_idx64;
    int s = (int)ld_idx(srcp, i, w64);
    int d = (int)ld_idx(dstp, i, w64);
    int pos = atomicAdd(&g_cur[d], 1);
    g_esrc[pos] = s;
}

// ---------------------------------------------------------------------------
// K5: one warp per dst node -- online softmax over its incoming edges.
//   e_j = <z_srcj, z_dst>;  out = sum exp(e_j - m) z_srcj / sum exp(e_j - m)
// No atomics; out written exactly once (zeros for empty segments).
// Software-pipelined: the gather for edge j+1 is issued before the
// shfl-reduce of edge j, hiding L2 latency behind the reduce/exp chain.
// ---------------------------------------------------------------------------
__global__ void __launch_bounds__(256) k_node(float* __restrict__ out) {
    int lane = threadIdx.x & 31;
    int n = (blockIdx.x * blockDim.x + threadIdx.x) >> 5;
    if (n >= N_NODES) return;

    int beg = g_off[n];
    int end = g_off[n + 1];

    float2 zd = ((const float2*)(g_z + (size_t)n * OUT_DIM))[lane];

    float m = -CUDART_INF_F;
    float den = 0.f;
    float a0 = 0.f, a1 = 0.f;

    float2 zs_cur = make_float2(0.f, 0.f);
    if (beg < end) {
        int s0 = g_esrc[beg];
        zs_cur = ((const float2*)(g_z + (size_t)s0 * OUT_DIM))[lane];
    }

    for (int j = beg; j < end; ++j) {
        float2 zs = zs_cur;
        if (j + 1 < end) {
            int sn = g_esrc[j + 1];           // uniform across warp (broadcast)
            zs_cur = ((const float2*)(g_z + (size_t)sn * OUT_DIM))[lane];
        }
        float p = zs.x * zd.x + zs.y * zd.y;
#pragma unroll
        for (int d = 16; d >= 1; d >>= 1)
            p += __shfl_xor_sync(0xffffffffu, p, d);
        float mn    = fmaxf(m, p);
        float scale = __expf(m - mn);         // exp(-inf)=0 on first edge
        float w     = __expf(p - mn);
        den = den * scale + w;
        a0  = a0  * scale + w * zs.x;
        a1  = a1  * scale + w * zs.y;
        m = mn;
    }

    float inv = (den > 0.f) ? __frcp_rn(den) : 0.f;
    ((float2*)(out + (size_t)n * OUT_DIM))[lane] = make_float2(a0 * inv, a1 * inv);
}

// ---------------------------------------------------------------------------
extern "C" void kernel_launch(void* const* d_in, const int* in_sizes, int n_in,
                              void* d_out, int out_size) {
    const float* h   = (const float*)d_in[0];
    const float* W   = (const float*)d_in[1];
    const void*  src = d_in[2];
    const void*  dst = d_in[3];
    float* out = (float*)d_out;

    k_init<<<(N_NODES + 255) / 256, 256>>>(src);
    k_gemm<<<(N_NODES + 63) / 64, 256>>>(h, W);
    k_hist<<<(N_EDGES + 255) / 256, 256>>>(dst);
    k_scan1<<<NBLK_SCAN, 256>>>();
    k_scan2<<<1, 128>>>();
    k_scan3<<<(N_NODES + 255) / 256, 256>>>();
    k_scatter<<<(N_EDGES + 255) / 256, 256>>>(src, dst);
    k_node<<<(N_NODES * 32 + 255) / 256, 256>>>(out);
}